// round 14
// baseline (speedup 1.0000x reference)
#include <cuda_runtime.h>
#include <cuda_bf16.h>
#include <cstdint>

#define B_  4
#define H_  16
#define LQ_ 2048
#define LK_ 2048
#define DM_ 1024
#define DK_ 64
#define DV_ 64

#define NROWS (B_ * H_ * LQ_)   // 131072 attention rows

// ---- device scratch (allocation-free rule: __device__ globals) ----
__device__ float g_Q[B_ * H_ * LQ_ * DK_];        // (B,H,LQ,DK)
__device__ float g_K[B_ * H_ * LK_ * DK_];        // (B,H,LK,DK)
__device__ float g_V[B_ * H_ * LK_ * DV_];        // (B,H,LK,DV)
__device__ float g_ctx[B_ * LQ_ * H_ * DV_];      // (B,LQ,H*DV)
__device__ float g_attn_fb[B_ * H_ * LQ_ * LK_];  // fallback attn scratch
__device__ float2 g_part[NROWS * 16];             // per-(row, col-tile) (max, sumexp)
__device__ float2 g_ms[NROWS];                    // per-row (max, 1/sum)

// ============================================================================
// Helpers
// ============================================================================
__device__ __forceinline__ void split2(float x, unsigned short& h, unsigned short& l) {
    __nv_bfloat16 bh = __float2bfloat16(x);
    float r = x - __bfloat162float(bh);
    __nv_bfloat16 bl = __float2bfloat16(r);
    h = __bfloat16_as_ushort(bh);
    l = __bfloat16_as_ushort(bl);
}

__device__ __forceinline__ void mma16816(float* c, const uint32_t* a, const uint32_t* b) {
    asm volatile(
        "mma.sync.aligned.m16n8k16.row.col.f32.bf16.bf16.f32 "
        "{%0,%1,%2,%3}, {%4,%5,%6,%7}, {%8,%9}, {%0,%1,%2,%3};"
        : "+f"(c[0]), "+f"(c[1]), "+f"(c[2]), "+f"(c[3])
        : "r"(a[0]), "r"(a[1]), "r"(a[2]), "r"(a[3]), "r"(b[0]), "r"(b[1]));
}

__device__ __forceinline__ uint32_t cvta_s(const void* p) {
    uint32_t a;
    asm("{ .reg .u64 t; cvta.to.shared.u64 t, %1; cvt.u32.u64 %0, t; }"
        : "=r"(a) : "l"(p));
    return a;
}

__device__ __forceinline__ void ldsm_x4(uint32_t* d, uint32_t addr) {
    asm volatile("ldmatrix.sync.aligned.m8n8.x4.shared.b16 {%0,%1,%2,%3}, [%4];"
                 : "=r"(d[0]), "=r"(d[1]), "=r"(d[2]), "=r"(d[3]) : "r"(addr));
}
__device__ __forceinline__ void ldsm_x2(uint32_t* d, uint32_t addr) {
    asm volatile("ldmatrix.sync.aligned.m8n8.x2.shared.b16 {%0,%1}, [%2];"
                 : "=r"(d[0]), "=r"(d[1]) : "r"(addr));
}

#define AROW(lane) (((lane) & 7) + (((lane) >> 3) & 1) * 8)
#define ACOL(lane) (((lane) >> 4) * 8)
#define BROW(lane) ((lane) & 7)
#define BCOL(lane) ((((lane) >> 3) & 1) * 8)

#define STRP 24  // padded row stride (ushorts) for 16-wide tiles

// ============================================================================
// Projection: Out[b,h,l,e] = sum_d A[b*LQ+l, d] * W[h,d,e]   (unchanged R13)
// ============================================================================
__global__ void __launch_bounds__(256) proj_tc(const float* __restrict__ A,
                                               const float* __restrict__ W,
                                               float* __restrict__ Out)
{
    __shared__ unsigned short Ah[2][128][STRP], Al[2][128][STRP];
    __shared__ unsigned short Bh[2][128][STRP], Bl[2][128][STRP];

    const int tid = threadIdx.x;
    const int wid = tid >> 5;
    const int lane = tid & 31;
    const int gid = lane >> 2;
    const int tig = lane & 3;
    const int wm = wid & 3;
    const int wn = wid >> 2;
    const int row0 = blockIdx.y * 128;
    const int col0 = blockIdx.x * 128;

    const uint32_t ah_u = cvta_s(Ah), al_u = cvta_s(Al);
    const uint32_t bh_u = cvta_s(Bh), bl_u = cvta_s(Bl);
    const uint32_t aoff = ((wm * 32 + AROW(lane)) * STRP + ACOL(lane)) * 2;
    const uint32_t boff = ((wn * 64 + BROW(lane)) * STRP + BCOL(lane)) * 2;
    const uint32_t BUFB = 128 * STRP * 2;

    const int ar0 = tid >> 2;
    const int ac0 = (tid & 3) << 2;
    const int bn = tid & 127;
    const int bkg = (tid >> 7) << 3;
    const int ng = col0 + bn;
    const int bh_ = ng >> 6, be = ng & 63;
    const float* wbase = &W[(size_t)(bh_ << 10) * 64 + be];

    float acc[2][8][4];
#pragma unroll
    for (int i = 0; i < 2; i++)
#pragma unroll
        for (int j = 0; j < 8; j++)
#pragma unroll
            for (int t = 0; t < 4; t++) acc[i][j][t] = 0.f;

    float4 va[2];
    float vb[8];

#pragma unroll
    for (int i = 0; i < 2; i++)
        va[i] = *(const float4*)&A[(size_t)(row0 + ar0 + i * 64) * DM_ + ac0];
#pragma unroll
    for (int j = 0; j < 8; j++) vb[j] = wbase[(size_t)(bkg + j) * 64];
#pragma unroll
    for (int i = 0; i < 2; i++) {
        ushort4 h, l;
        split2(va[i].x, h.x, l.x); split2(va[i].y, h.y, l.y);
        split2(va[i].z, h.z, l.z); split2(va[i].w, h.w, l.w);
        *(ushort4*)&Ah[0][ar0 + i * 64][ac0] = h;
        *(ushort4*)&Al[0][ar0 + i * 64][ac0] = l;
    }
#pragma unroll
    for (int j = 0; j < 8; j++) split2(vb[j], Bh[0][bn][bkg + j], Bl[0][bn][bkg + j]);
    __syncthreads();

    const int NSTEP = DM_ / 16;
    for (int s = 0; s < NSTEP; s++) {
        const int buf = s & 1;
        const int k1 = (s + 1) * 16;
        if (s + 1 < NSTEP) {
#pragma unroll
            for (int i = 0; i < 2; i++)
                va[i] = *(const float4*)&A[(size_t)(row0 + ar0 + i * 64) * DM_ + k1 + ac0];
#pragma unroll
            for (int j = 0; j < 8; j++) vb[j] = wbase[(size_t)(k1 + bkg + j) * 64];
        }

        const uint32_t ab = buf * BUFB;
        uint32_t ah[2][4], al[2][4];
#pragma unroll
        for (int mi = 0; mi < 2; mi++) {
            ldsm_x4(ah[mi], ah_u + ab + aoff + mi * (16 * STRP * 2));
            ldsm_x4(al[mi], al_u + ab + aoff + mi * (16 * STRP * 2));
        }
        uint32_t bhf[8][2], blf[8][2];
#pragma unroll
        for (int ni = 0; ni < 8; ni++) {
            ldsm_x2(bhf[ni], bh_u + ab + boff + ni * (8 * STRP * 2));
            ldsm_x2(blf[ni], bl_u + ab + boff + ni * (8 * STRP * 2));
        }
#pragma unroll
        for (int ni = 0; ni < 8; ni++)
#pragma unroll
            for (int mi = 0; mi < 2; mi++) {
                mma16816(acc[mi][ni], ah[mi], bhf[ni]);
                mma16816(acc[mi][ni], ah[mi], blf[ni]);
                mma16816(acc[mi][ni], al[mi], bhf[ni]);
            }

        if (s + 1 < NSTEP) {
            const int nb = buf ^ 1;
#pragma unroll
            for (int i = 0; i < 2; i++) {
                ushort4 h, l;
                split2(va[i].x, h.x, l.x); split2(va[i].y, h.y, l.y);
                split2(va[i].z, h.z, l.z); split2(va[i].w, h.w, l.w);
                *(ushort4*)&Ah[nb][ar0 + i * 64][ac0] = h;
                *(ushort4*)&Al[nb][ar0 + i * 64][ac0] = l;
            }
#pragma unroll
            for (int j = 0; j < 8; j++)
                split2(vb[j], Bh[nb][bn][bkg + j], Bl[nb][bn][bkg + j]);
        }
        __syncthreads();
    }

#pragma unroll
    for (int mi = 0; mi < 2; mi++) {
#pragma unroll
        for (int ni = 0; ni < 8; ni++) {
            int n = col0 + wn * 64 + ni * 8 + 2 * tig;
            int hh = n >> 6, e = n & 63;
            int row = row0 + wm * 32 + mi * 16 + gid;
            int b = row >> 11, l = row & 2047;
            size_t base = (size_t)((b << 4) + hh) * 2048 + l;
            *(float2*)&Out[base * 64 + e] = make_float2(acc[mi][ni][0], acc[mi][ni][1]);
            row += 8;
            b = row >> 11; l = row & 2047;
            base = (size_t)((b << 4) + hh) * 2048 + l;
            *(float2*)&Out[base * 64 + e] = make_float2(acc[mi][ni][2], acc[mi][ni][3]);
        }
    }
}

// ============================================================================
// Scores v3: 128x128 whole-K tiles, 2 CTAs/SM (reg cap 128), raw S write +
// per-row (max, sumexp) partials for fused softmax.
// smem: Qh/Ql[128][72], Kh/Kl[128][72] = 73728 B dynamic.
// ============================================================================
#define SC_STR 72
#define SC_SMEM_BYTES (4 * 128 * SC_STR * 2)  // 73728

__global__ void __launch_bounds__(256, 2) scores_tc(const float* __restrict__ Q,
                                                    const float* __restrict__ K,
                                                    float* __restrict__ S)
{
    extern __shared__ unsigned short sm[];
    unsigned short* Qh = sm;
    unsigned short* Ql = sm + 128 * SC_STR;
    unsigned short* Kh = sm + 2 * 128 * SC_STR;
    unsigned short* Kl = sm + 3 * 128 * SC_STR;
    __shared__ float2 sst[2][128];

    const int tid = threadIdx.x;
    const int wid = tid >> 5;
    const int lane = tid & 31;
    const int gid = lane >> 2;
    const int tig = lane & 3;
    const int wm = wid & 3;
    const int wn = wid >> 2;  // 0/1
    const int bh = blockIdx.z;
    const int row0 = blockIdx.y * 128;
    const int col0 = blockIdx.x * 128;
    const float* Qb = Q + (size_t)bh * LQ_ * DK_;
    const float* Kb = K + (size_t)bh * LK_ * DK_;

#pragma unroll
    for (int i = 0; i < 8; i++) {
        int idx = tid + i * 256;
        int r = idx >> 4;
        int c4 = (idx & 15) << 2;
        float4 v = *(const float4*)&Qb[(size_t)(row0 + r) * 64 + c4];
        ushort4 h, l;
        split2(v.x, h.x, l.x); split2(v.y, h.y, l.y);
        split2(v.z, h.z, l.z); split2(v.w, h.w, l.w);
        *(ushort4*)&Qh[r * SC_STR + c4] = h;
        *(ushort4*)&Ql[r * SC_STR + c4] = l;
        float4 w = *(const float4*)&Kb[(size_t)(col0 + r) * 64 + c4];
        split2(w.x, h.x, l.x); split2(w.y, h.y, l.y);
        split2(w.z, h.z, l.z); split2(w.w, h.w, l.w);
        *(ushort4*)&Kh[r * SC_STR + c4] = h;
        *(ushort4*)&Kl[r * SC_STR + c4] = l;
    }
    __syncthreads();

    const uint32_t qh_u = cvta_s(Qh), ql_u = cvta_s(Ql);
    const uint32_t kh_u = cvta_s(Kh), kl_u = cvta_s(Kl);
    const uint32_t aoff = ((wm * 32 + AROW(lane)) * SC_STR + ACOL(lane)) * 2;
    const uint32_t boff = ((wn * 64 + BROW(lane)) * SC_STR + BCOL(lane)) * 2;

    float acc[2][8][4];
#pragma unroll
    for (int i = 0; i < 2; i++)
#pragma unroll
        for (int j = 0; j < 8; j++)
#pragma unroll
            for (int t = 0; t < 4; t++) acc[i][j][t] = 0.f;

#pragma unroll
    for (int ks = 0; ks < 4; ks++) {
        const uint32_t kb = ks * 32;
        uint32_t ah[2][4], al[2][4];
#pragma unroll
        for (int mi = 0; mi < 2; mi++) {
            ldsm_x4(ah[mi], qh_u + aoff + mi * (16 * SC_STR * 2) + kb);
            ldsm_x4(al[mi], ql_u + aoff + mi * (16 * SC_STR * 2) + kb);
        }
        // B frags in chunks of 4 (register cap)
#pragma unroll
        for (int ng = 0; ng < 2; ng++) {
            uint32_t bhf[4][2], blf[4][2];
#pragma unroll
            for (int j = 0; j < 4; j++) {
                ldsm_x2(bhf[j], kh_u + boff + (ng * 4 + j) * (8 * SC_STR * 2) + kb);
                ldsm_x2(blf[j], kl_u + boff + (ng * 4 + j) * (8 * SC_STR * 2) + kb);
            }
#pragma unroll
            for (int j = 0; j < 4; j++)
#pragma unroll
                for (int mi = 0; mi < 2; mi++) {
                    mma16816(acc[mi][ng * 4 + j], ah[mi], bhf[j]);
                    mma16816(acc[mi][ng * 4 + j], ah[mi], blf[j]);
                    mma16816(acc[mi][ng * 4 + j], al[mi], bhf[j]);
                }
        }
    }

    // scale in place
#pragma unroll
    for (int i = 0; i < 2; i++)
#pragma unroll
        for (int j = 0; j < 8; j++)
#pragma unroll
            for (int t = 0; t < 4; t++) acc[i][j][t] *= 0.125f;

    float* Sb = S + (size_t)bh * LQ_ * LK_;

    // raw S store (shfl-widened float4)
#pragma unroll
    for (int mi = 0; mi < 2; mi++) {
#pragma unroll
        for (int ni = 0; ni < 8; ni++) {
            float c0 = acc[mi][ni][0], c1 = acc[mi][ni][1];
            float c2 = acc[mi][ni][2], c3 = acc[mi][ni][3];
            float p0 = __shfl_xor_sync(0xffffffffu, c0, 1);
            float p1 = __shfl_xor_sync(0xffffffffu, c1, 1);
            float p2 = __shfl_xor_sync(0xffffffffu, c2, 1);
            float p3 = __shfl_xor_sync(0xffffffffu, c3, 1);
            int row = row0 + wm * 32 + mi * 16 + gid;
            int colb = col0 + wn * 64 + ni * 8 + (tig >> 1) * 4;
            if ((lane & 1) == 0) {
                *(float4*)&Sb[(size_t)row * LK_ + colb] = make_float4(c0, c1, p0, p1);
            } else {
                *(float4*)&Sb[(size_t)(row + 8) * LK_ + colb] = make_float4(p2, p3, c2, c3);
            }
        }
    }

    // per-row (max, sumexp) over this warp's 64 cols
#pragma unroll
    for (int mi = 0; mi < 2; mi++) {
        float mA = -1e30f, mB = -1e30f;
#pragma unroll
        for (int ni = 0; ni < 8; ni++) {
            mA = fmaxf(mA, fmaxf(acc[mi][ni][0], acc[mi][ni][1]));
            mB = fmaxf(mB, fmaxf(acc[mi][ni][2], acc[mi][ni][3]));
        }
        mA = fmaxf(mA, __shfl_xor_sync(0xffffffffu, mA, 1));
        mA = fmaxf(mA, __shfl_xor_sync(0xffffffffu, mA, 2));
        mB = fmaxf(mB, __shfl_xor_sync(0xffffffffu, mB, 1));
        mB = fmaxf(mB, __shfl_xor_sync(0xffffffffu, mB, 2));
        float sA = 0.f, sB = 0.f;
#pragma unroll
        for (int ni = 0; ni < 8; ni++) {
            sA += __expf(acc[mi][ni][0] - mA) + __expf(acc[mi][ni][1] - mA);
            sB += __expf(acc[mi][ni][2] - mB) + __expf(acc[mi][ni][3] - mB);
        }
        sA += __shfl_xor_sync(0xffffffffu, sA, 1);
        sA += __shfl_xor_sync(0xffffffffu, sA, 2);
        sB += __shfl_xor_sync(0xffffffffu, sB, 1);
        sB += __shfl_xor_sync(0xffffffffu, sB, 2);
        if (tig == 0) {
            sst[wn][wm * 32 + mi * 16 + gid] = make_float2(mA, sA);
            sst[wn][wm * 32 + mi * 16 + gid + 8] = make_float2(mB, sB);
        }
    }
    __syncthreads();
    if (tid < 128) {
        float2 a = sst[0][tid], b = sst[1][tid];
        float M = fmaxf(a.x, b.x);
        float Ssum = a.y * __expf(a.x - M) + b.y * __expf(b.x - M);
        g_part[((size_t)(bh * 2048 + row0 + tid) << 4) + blockIdx.x] = make_float2(M, Ssum);
    }
}

// ============================================================================
// Stats reduce: 16 partials per row -> (max, 1/sum). Fixed order: deterministic.
// ============================================================================
__global__ void __launch_bounds__(256) stats_reduce()
{
    int row = blockIdx.x * 256 + threadIdx.x;
    const float2* p = &g_part[(size_t)row << 4];
    float M = -1e30f;
#pragma unroll
    for (int i = 0; i < 16; i++) M = fmaxf(M, p[i].x);
    float Ssum = 0.f;
#pragma unroll
    for (int i = 0; i < 16; i++) Ssum += p[i].y * __expf(p[i].x - M);
    g_ms[row] = make_float2(M, 1.0f / Ssum);
}

// ============================================================================
// Context (fused softmax): reads raw S, computes p = exp(s-m)*inv on the fly,
// writes p in-place (attn output), accumulates ctx = p @ V.
// Block 128x64, k-step 16 (128 steps), double-buffered, ldmatrix frags.
// ============================================================================
__global__ void __launch_bounds__(256) ctx_tc(float* __restrict__ P,
                                              const float* __restrict__ V)
{
    __shared__ unsigned short Ah[2][128][STRP], Al[2][128][STRP];
    __shared__ unsigned short Bh[2][64][STRP], Bl[2][64][STRP];
    __shared__ float2 ms[128];

    const int tid = threadIdx.x;
    const int wid = tid >> 5;
    const int lane = tid & 31;
    const int gid = lane >> 2;
    const int tig = lane & 3;
    const int bh = blockIdx.z;
    const int row0 = blockIdx.y * 128;
    float* Pb = P + (size_t)bh * LQ_ * LK_;
    const float* Vb = V + (size_t)bh * LK_ * DV_;

    if (tid < 128) ms[tid] = g_ms[bh * 2048 + row0 + tid];
    __syncthreads();

    const uint32_t ah_u = cvta_s(Ah), al_u = cvta_s(Al);
    const uint32_t bh_u = cvta_s(Bh), bl_u = cvta_s(Bl);
    const uint32_t aoff = ((wid * 16 + AROW(lane)) * STRP + ACOL(lane)) * 2;
    const uint32_t boff = (BROW(lane) * STRP + BCOL(lane)) * 2;
    const uint32_t ABUF = 128 * STRP * 2;
    const uint32_t BBUF = 64 * STRP * 2;

    const int ar0 = tid >> 2;
    const int ac0 = (tid & 3) << 2;
    const int bn = tid & 63;
    const int bkg = (tid >> 6) << 2;

    const float2 ms0 = ms[ar0];
    const float2 ms1 = ms[ar0 + 64];

    float acc[8][4];
#pragma unroll
    for (int j = 0; j < 8; j++)
#pragma unroll
        for (int t = 0; t < 4; t++) acc[j][t] = 0.f;

    float4 va[2];
    float vb[4];

    // prologue k=0: load S, exp-normalize, write attn in place
#pragma unroll
    for (int i = 0; i < 2; i++) {
        size_t off = (size_t)(row0 + ar0 + i * 64) * LK_ + ac0;
        float4 v = *(const float4*)&Pb[off];
        float2 mr = (i == 0) ? ms0 : ms1;
        v.x = __expf(v.x - mr.x) * mr.y;
        v.y = __expf(v.y - mr.x) * mr.y;
        v.z = __expf(v.z - mr.x) * mr.y;
        v.w = __expf(v.w - mr.x) * mr.y;
        *(float4*)&Pb[off] = v;
        va[i] = v;
    }
#pragma unroll
    for (int j = 0; j < 4; j++) vb[j] = Vb[(size_t)(bkg + j) * 64 + bn];
#pragma unroll
    for (int i = 0; i < 2; i++) {
        ushort4 h, l;
        split2(va[i].x, h.x, l.x); split2(va[i].y, h.y, l.y);
        split2(va[i].z, h.z, l.z); split2(va[i].w, h.w, l.w);
        *(ushort4*)&Ah[0][ar0 + i * 64][ac0] = h;
        *(ushort4*)&Al[0][ar0 + i * 64][ac0] = l;
    }
#pragma unroll
    for (int j = 0; j < 4; j++) split2(vb[j], Bh[0][bn][bkg + j], Bl[0][bn][bkg + j]);
    __syncthreads();

    const int NSTEP = LK_ / 16;  // 128
    for (int s = 0; s < NSTEP; s++) {
        const int buf = s & 1;
        const int k1 = (s + 1) * 16;
        if (s + 1 < NSTEP) {
#pragma unroll
            for (int i = 0; i < 2; i++) {
                size_t off = (size_t)(row0 + ar0 + i * 64) * LK_ + k1 + ac0;
                float4 v = *(const float4*)&Pb[off];
                float2 mr = (i == 0) ? ms0 : ms1;
                v.x = __expf(v.x - mr.x) * mr.y;
                v.y = __expf(v.y - mr.x) * mr.y;
                v.z = __expf(v.z - mr.x) * mr.y;
                v.w = __expf(v.w - mr.x) * mr.y;
                *(float4*)&Pb[off] = v;
                va[i] = v;
            }
#pragma unroll
            for (int j = 0; j < 4; j++) vb[j] = Vb[(size_t)(k1 + bkg + j) * 64 + bn];
        }

        uint32_t ah[4], al[4];
        ldsm_x4(ah, ah_u + buf * ABUF + aoff);
        ldsm_x4(al, al_u + buf * ABUF + aoff);
        uint32_t bhf[8][2], blf[8][2];
#pragma unroll
        for (int ni = 0; ni < 8; ni++) {
            ldsm_x2(bhf[ni], bh_u + buf * BBUF + boff + ni * (8 * STRP * 2));
            ldsm_x2(blf[ni], bl_u + buf * BBUF + boff + ni * (8 * STRP * 2));
        }
#pragma unroll
        for (int ni = 0; ni < 8; ni++) {
            mma16816(acc[ni], ah, bhf[ni]);
            mma16816(acc[ni], ah, blf[ni]);
            mma16816(acc[ni], al, bhf[ni]);
        }

        if (s + 1 < NSTEP) {
            const int nb = buf ^ 1;
#pragma unroll
            for (int i = 0; i < 2; i++) {
                ushort4 h, l;
                split2(va[i].x, h.x, l.x); split2(va[i].y, h.y, l.y);
                split2(va[i].z, h.z, l.z); split2(va[i].w, h.w, l.w);
                *(ushort4*)&Ah[nb][ar0 + i * 64][ac0] = h;
                *(ushort4*)&Al[nb][ar0 + i * 64][ac0] = l;
            }
#pragma unroll
            for (int j = 0; j < 4; j++)
                split2(vb[j], Bh[nb][bn][bkg + j], Bl[nb][bn][bkg + j]);
        }
        __syncthreads();
    }

    const int b = bh >> 4, hh = bh & 15;
#pragma unroll
    for (int ni = 0; ni < 8; ni++) {
        int row = row0 + wid * 16 + gid;
        int col = hh * 64 + ni * 8 + 2 * tig;
        *(float2*)&g_ctx[(size_t)(b * 2048 + row) * 1024 + col] =
            make_float2(acc[ni][0], acc[ni][1]);
        *(float2*)&g_ctx[(size_t)(b * 2048 + row + 8) * 1024 + col] =
            make_float2(acc[ni][2], acc[ni][3]);
    }
}

// ============================================================================
// Output projection: out = ctx @ wo; M=8192, N=K=1024.   (unchanged R13)
// ============================================================================
__global__ void __launch_bounds__(256) outproj_tc(const float* __restrict__ W,
                                                  float* __restrict__ C)
{
    __shared__ unsigned short Ah[2][128][STRP], Al[2][128][STRP];
    __shared__ unsigned short Bh[2][128][STRP], Bl[2][128][STRP];

    const int tid = threadIdx.x;
    const int wid = tid >> 5;
    const int lane = tid & 31;
    const int gid = lane >> 2;
    const int tig = lane & 3;
    const int wm = wid & 3;
    const int wn = wid >> 2;
    const int row0 = blockIdx.y * 128;
    const int col0 = blockIdx.x * 128;

    const uint32_t ah_u = cvta_s(Ah), al_u = cvta_s(Al);
    const uint32_t bh_u = cvta_s(Bh), bl_u = cvta_s(Bl);
    const uint32_t aoff = ((wm * 32 + AROW(lane)) * STRP + ACOL(lane)) * 2;
    const uint32_t boff = ((wn * 64 + BROW(lane)) * STRP + BCOL(lane)) * 2;
    const uint32_t BUFB = 128 * STRP * 2;

    const int ar0 = tid >> 2;
    const int ac0 = (tid & 3) << 2;
    const int bn = tid & 127;
    const int bkg = (tid >> 7) << 3;

    float acc[2][8][4];
#pragma unroll
    for (int i = 0; i < 2; i++)
#pragma unroll
        for (int j = 0; j < 8; j++)
#pragma unroll
            for (int t = 0; t < 4; t++) acc[i][j][t] = 0.f;

    float4 va[2];
    float vb[8];

#pragma unroll
    for (int i = 0; i < 2; i++)
        va[i] = *(const float4*)&g_ctx[(size_t)(row0 + ar0 + i * 64) * DM_ + ac0];
#pragma unroll
    for (int j = 0; j < 8; j++) vb[j] = W[(size_t)(bkg + j) * DM_ + col0 + bn];
#pragma unroll
    for (int i = 0; i < 2; i++) {
        ushort4 h, l;
        split2(va[i].x, h.x, l.x); split2(va[i].y, h.y, l.y);
        split2(va[i].z, h.z, l.z); split2(va[i].w, h.w, l.w);
        *(ushort4*)&Ah[0][ar0 + i * 64][ac0] = h;
        *(ushort4*)&Al[0][ar0 + i * 64][ac0] = l;
    }
#pragma unroll
    for (int j = 0; j < 8; j++) split2(vb[j], Bh[0][bn][bkg + j], Bl[0][bn][bkg + j]);
    __syncthreads();

    const int NSTEP = DM_ / 16;
    for (int s = 0; s < NSTEP; s++) {
        const int buf = s & 1;
        const int k1 = (s + 1) * 16;
        if (s + 1 < NSTEP) {
#pragma unroll
            for (int i = 0; i < 2; i++)
                va[i] = *(const float4*)&g_ctx[(size_t)(row0 + ar0 + i * 64) * DM_ + k1 + ac0];
#pragma unroll
            for (int j = 0; j < 8; j++) vb[j] = W[(size_t)(k1 + bkg + j) * DM_ + col0 + bn];
        }

        const uint32_t ab = buf * BUFB;
        uint32_t ah[2][4], al[2][4];
#pragma unroll
        for (int mi = 0; mi < 2; mi++) {
            ldsm_x4(ah[mi], ah_u + ab + aoff + mi * (16 * STRP * 2));
            ldsm_x4(al[mi], al_u + ab + aoff + mi * (16 * STRP * 2));
        }
        uint32_t bhf[8][2], blf[8][2];
#pragma unroll
        for (int ni = 0; ni < 8; ni++) {
            ldsm_x2(bhf[ni], bh_u + ab + boff + ni * (8 * STRP * 2));
            ldsm_x2(blf[ni], bl_u + ab + boff + ni * (8 * STRP * 2));
        }
#pragma unroll
        for (int ni = 0; ni < 8; ni++)
#pragma unroll
            for (int mi = 0; mi < 2; mi++) {
                mma16816(acc[mi][ni], ah[mi], bhf[ni]);
                mma16816(acc[mi][ni], ah[mi], blf[ni]);
                mma16816(acc[mi][ni], al[mi], bhf[ni]);
            }

        if (s + 1 < NSTEP) {
            const int nb = buf ^ 1;
#pragma unroll
            for (int i = 0; i < 2; i++) {
                ushort4 h, l;
                split2(va[i].x, h.x, l.x); split2(va[i].y, h.y, l.y);
                split2(va[i].z, h.z, l.z); split2(va[i].w, h.w, l.w);
                *(ushort4*)&Ah[nb][ar0 + i * 64][ac0] = h;
                *(ushort4*)&Al[nb][ar0 + i * 64][ac0] = l;
            }
#pragma unroll
            for (int j = 0; j < 8; j++)
                split2(vb[j], Bh[nb][bn][bkg + j], Bl[nb][bn][bkg + j]);
        }
        __syncthreads();
    }

#pragma unroll
    for (int mi = 0; mi < 2; mi++) {
#pragma unroll
        for (int ni = 0; ni < 8; ni++) {
            int row = row0 + wm * 32 + mi * 16 + gid;
            int col = col0 + wn * 64 + ni * 8 + 2 * tig;
            *(float2*)&C[(size_t)row * DM_ + col] =
                make_float2(acc[mi][ni][0], acc[mi][ni][1]);
            *(float2*)&C[(size_t)(row + 8) * DM_ + col] =
                make_float2(acc[mi][ni][2], acc[mi][ni][3]);
        }
    }
}

// ============================================================================
// Launch
// ============================================================================
extern "C" void kernel_launch(void* const* d_in, const int* in_sizes, int n_in,
                              void* d_out, int out_size)
{
    const float* q  = (const float*)d_in[0];
    const float* k  = (const float*)d_in[1];
    const float* v  = (const float*)d_in[2];
    const float* wq = (const float*)d_in[3];
    const float* wk = (const float*)d_in[4];
    const float* wv = (const float*)d_in[5];
    const float* wo = (const float*)d_in[6];
    float* out = (float*)d_out;

    const long long OUT_E = (long long)B_ * LQ_ * DM_;        // 8,388,608
    const long long ATT_E = (long long)B_ * H_ * LQ_ * LK_;   // 268,435,456

    float* attn;
    if ((long long)out_size >= OUT_E + ATT_E) {
        attn = out + OUT_E;                 // tuple output: [out, attn]
    } else {
        void* p = nullptr;
        cudaGetSymbolAddress(&p, g_attn_fb);
        attn = (float*)p;
    }

    float *gq, *gk, *gv;
    cudaGetSymbolAddress((void**)&gq, g_Q);
    cudaGetSymbolAddress((void**)&gk, g_K);
    cudaGetSymbolAddress((void**)&gv, g_V);

    cudaFuncSetAttribute(scores_tc,
                         cudaFuncAttributeMaxDynamicSharedMemorySize, SC_SMEM_BYTES);

    dim3 t(256);
    proj_tc<<<dim3(8, 64), t>>>(q, wq, gq);
    proj_tc<<<dim3(8, 64), t>>>(k, wk, gk);
    proj_tc<<<dim3(8, 64), t>>>(v, wv, gv);
    scores_tc<<<dim3(16, 16, 64), t, SC_SMEM_BYTES>>>(gq, gk, attn);
    stats_reduce<<<dim3(NROWS / 256), t>>>();
    ctx_tc<<<dim3(1, 16, 64), t>>>(attn, gv);
    outproj_tc<<<dim3(8, 64), t>>>(wo, out);
}

// round 17
// speedup vs baseline: 1.0599x; 1.0599x over previous
#include <cuda_runtime.h>
#include <cuda_bf16.h>
#include <cstdint>

#define B_  4
#define H_  16
#define LQ_ 2048
#define LK_ 2048
#define DM_ 1024
#define DK_ 64
#define DV_ 64

#define NROWS (B_ * H_ * LQ_)   // 131072 attention rows

// ---- device scratch (allocation-free rule: __device__ globals) ----
__device__ float g_Q[B_ * H_ * LQ_ * DK_];        // (B,H,LQ,DK)
__device__ float g_K[B_ * H_ * LK_ * DK_];        // (B,H,LK,DK)
__device__ float g_V[B_ * H_ * LK_ * DV_];        // (B,H,LK,DV)
__device__ float g_ctx[B_ * LQ_ * H_ * DV_];      // (B,LQ,H*DV)
__device__ float g_attn_fb[B_ * H_ * LQ_ * LK_];  // fallback attn scratch
__device__ float2 g_part[NROWS * 8];              // per-(row, 256col-tile) (max, sumexp)
__device__ float2 g_ms[NROWS];                    // per-row (max, 1/sum)

// ============================================================================
// Helpers
// ============================================================================
__device__ __forceinline__ void split2(float x, unsigned short& h, unsigned short& l) {
    __nv_bfloat16 bh = __float2bfloat16(x);
    float r = x - __bfloat162float(bh);
    __nv_bfloat16 bl = __float2bfloat16(r);
    h = __bfloat16_as_ushort(bh);
    l = __bfloat16_as_ushort(bl);
}

__device__ __forceinline__ void mma16816(float* c, const uint32_t* a, const uint32_t* b) {
    asm volatile(
        "mma.sync.aligned.m16n8k16.row.col.f32.bf16.bf16.f32 "
        "{%0,%1,%2,%3}, {%4,%5,%6,%7}, {%8,%9}, {%0,%1,%2,%3};"
        : "+f"(c[0]), "+f"(c[1]), "+f"(c[2]), "+f"(c[3])
        : "r"(a[0]), "r"(a[1]), "r"(a[2]), "r"(a[3]), "r"(b[0]), "r"(b[1]));
}

__device__ __forceinline__ uint32_t cvta_s(const void* p) {
    uint32_t a;
    asm("{ .reg .u64 t; cvta.to.shared.u64 t, %1; cvt.u32.u64 %0, t; }"
        : "=r"(a) : "l"(p));
    return a;
}

__device__ __forceinline__ void ldsm_x4(uint32_t* d, uint32_t addr) {
    asm volatile("ldmatrix.sync.aligned.m8n8.x4.shared.b16 {%0,%1,%2,%3}, [%4];"
                 : "=r"(d[0]), "=r"(d[1]), "=r"(d[2]), "=r"(d[3]) : "r"(addr));
}
__device__ __forceinline__ void ldsm_x2(uint32_t* d, uint32_t addr) {
    asm volatile("ldmatrix.sync.aligned.m8n8.x2.shared.b16 {%0,%1}, [%2];"
                 : "=r"(d[0]), "=r"(d[1]) : "r"(addr));
}

#define AROW(lane) (((lane) & 7) + (((lane) >> 3) & 1) * 8)
#define ACOL(lane) (((lane) >> 4) * 8)
#define BROW(lane) ((lane) & 7)
#define BCOL(lane) ((((lane) >> 3) & 1) * 8)

#define STRP 24  // padded row stride (ushorts) for 16-wide tiles

// ============================================================================
// Projection: Out[b,h,l,e] = sum_d A[b*LQ+l, d] * W[h,d,e]
// Block 128x128, k-step 16, double-buffered, 2 CTAs/SM, chunked B-frags.
// ============================================================================
__global__ void __launch_bounds__(256, 2) proj_tc(const float* __restrict__ A,
                                                  const float* __restrict__ W,
                                                  float* __restrict__ Out)
{
    __shared__ unsigned short Ah[2][128][STRP], Al[2][128][STRP];
    __shared__ unsigned short Bh[2][128][STRP], Bl[2][128][STRP];

    const int tid = threadIdx.x;
    const int wid = tid >> 5;
    const int lane = tid & 31;
    const int gid = lane >> 2;
    const int tig = lane & 3;
    const int wm = wid & 3;
    const int wn = wid >> 2;
    const int row0 = blockIdx.y * 128;
    const int col0 = blockIdx.x * 128;

    const uint32_t ah_u = cvta_s(Ah), al_u = cvta_s(Al);
    const uint32_t bh_u = cvta_s(Bh), bl_u = cvta_s(Bl);
    const uint32_t aoff = ((wm * 32 + AROW(lane)) * STRP + ACOL(lane)) * 2;
    const uint32_t boff = ((wn * 64 + BROW(lane)) * STRP + BCOL(lane)) * 2;
    const uint32_t BUFB = 128 * STRP * 2;

    const int ar0 = tid >> 2;
    const int ac0 = (tid & 3) << 2;
    const int bn = tid & 127;
    const int bkg = (tid >> 7) << 3;
    const int ng_ = col0 + bn;
    const int bh_ = ng_ >> 6, be = ng_ & 63;
    const float* wbase = &W[(size_t)(bh_ << 10) * 64 + be];

    float acc[2][8][4];
#pragma unroll
    for (int i = 0; i < 2; i++)
#pragma unroll
        for (int j = 0; j < 8; j++)
#pragma unroll
            for (int t = 0; t < 4; t++) acc[i][j][t] = 0.f;

    float4 va[2];
    float vb[8];

#pragma unroll
    for (int i = 0; i < 2; i++)
        va[i] = *(const float4*)&A[(size_t)(row0 + ar0 + i * 64) * DM_ + ac0];
#pragma unroll
    for (int j = 0; j < 8; j++) vb[j] = wbase[(size_t)(bkg + j) * 64];
#pragma unroll
    for (int i = 0; i < 2; i++) {
        ushort4 h, l;
        split2(va[i].x, h.x, l.x); split2(va[i].y, h.y, l.y);
        split2(va[i].z, h.z, l.z); split2(va[i].w, h.w, l.w);
        *(ushort4*)&Ah[0][ar0 + i * 64][ac0] = h;
        *(ushort4*)&Al[0][ar0 + i * 64][ac0] = l;
    }
#pragma unroll
    for (int j = 0; j < 8; j++) split2(vb[j], Bh[0][bn][bkg + j], Bl[0][bn][bkg + j]);
    __syncthreads();

    const int NSTEP = DM_ / 16;
    for (int s = 0; s < NSTEP; s++) {
        const int buf = s & 1;
        const int k1 = (s + 1) * 16;
        if (s + 1 < NSTEP) {
#pragma unroll
            for (int i = 0; i < 2; i++)
                va[i] = *(const float4*)&A[(size_t)(row0 + ar0 + i * 64) * DM_ + k1 + ac0];
#pragma unroll
            for (int j = 0; j < 8; j++) vb[j] = wbase[(size_t)(k1 + bkg + j) * 64];
        }

        const uint32_t ab = buf * BUFB;
        uint32_t ah[2][4], al[2][4];
#pragma unroll
        for (int mi = 0; mi < 2; mi++) {
            ldsm_x4(ah[mi], ah_u + ab + aoff + mi * (16 * STRP * 2));
            ldsm_x4(al[mi], al_u + ab + aoff + mi * (16 * STRP * 2));
        }
#pragma unroll
        for (int ng = 0; ng < 2; ng++) {
            uint32_t bhf[4][2], blf[4][2];
#pragma unroll
            for (int j = 0; j < 4; j++) {
                ldsm_x2(bhf[j], bh_u + ab + boff + (ng * 4 + j) * (8 * STRP * 2));
                ldsm_x2(blf[j], bl_u + ab + boff + (ng * 4 + j) * (8 * STRP * 2));
            }
#pragma unroll
            for (int j = 0; j < 4; j++)
#pragma unroll
                for (int mi = 0; mi < 2; mi++) {
                    mma16816(acc[mi][ng * 4 + j], ah[mi], bhf[j]);
                    mma16816(acc[mi][ng * 4 + j], ah[mi], blf[j]);
                    mma16816(acc[mi][ng * 4 + j], al[mi], bhf[j]);
                }
        }

        if (s + 1 < NSTEP) {
            const int nb = buf ^ 1;
#pragma unroll
            for (int i = 0; i < 2; i++) {
                ushort4 h, l;
                split2(va[i].x, h.x, l.x); split2(va[i].y, h.y, l.y);
                split2(va[i].z, h.z, l.z); split2(va[i].w, h.w, l.w);
                *(ushort4*)&Ah[nb][ar0 + i * 64][ac0] = h;
                *(ushort4*)&Al[nb][ar0 + i * 64][ac0] = l;
            }
#pragma unroll
            for (int j = 0; j < 8; j++)
                split2(vb[j], Bh[nb][bn][bkg + j], Bl[nb][bn][bkg + j]);
        }
        __syncthreads();
    }

#pragma unroll
    for (int mi = 0; mi < 2; mi++) {
#pragma unroll
        for (int ni = 0; ni < 8; ni++) {
            int n = col0 + wn * 64 + ni * 8 + 2 * tig;
            int hh = n >> 6, e = n & 63;
            int row = row0 + wm * 32 + mi * 16 + gid;
            int b = row >> 11, l = row & 2047;
            size_t base = (size_t)((b << 4) + hh) * 2048 + l;
            *(float2*)&Out[base * 64 + e] = make_float2(acc[mi][ni][0], acc[mi][ni][1]);
            row += 8;
            b = row >> 11; l = row & 2047;
            base = (size_t)((b << 4) + hh) * 2048 + l;
            *(float2*)&Out[base * 64 + e] = make_float2(acc[mi][ni][2], acc[mi][ni][3]);
        }
    }
}

// ============================================================================
// Scores: 128x256 whole-K tiles (R13 best) + per-row (max,sumexp) partials.
// smem: Qh/Ql[128][72], Kh/Kl[256][72] = 110592 B dynamic, 1 CTA/SM.
// ============================================================================
#define SC_STR 72
#define SC_SMEM_BYTES ((2 * 128 * SC_STR + 2 * 256 * SC_STR) * 2)  // 110592

__global__ void __launch_bounds__(256) scores_tc(const float* __restrict__ Q,
                                                 const float* __restrict__ K,
                                                 float* __restrict__ S)
{
    extern __shared__ unsigned short sm[];
    unsigned short* Qh = sm;
    unsigned short* Ql = sm + 128 * SC_STR;
    unsigned short* Kh = sm + 2 * 128 * SC_STR;
    unsigned short* Kl = sm + 2 * 128 * SC_STR + 256 * SC_STR;
    __shared__ float2 sst[2][128];

    const int tid = threadIdx.x;
    const int wid = tid >> 5;
    const int lane = tid & 31;
    const int gid = lane >> 2;
    const int tig = lane & 3;
    const int wm = wid & 3;
    const int wn = wid >> 2;
    const int bh = blockIdx.z;
    const int row0 = blockIdx.y * 128;
    const int col0 = blockIdx.x * 256;
    const float* Qb = Q + (size_t)bh * LQ_ * DK_;
    const float* Kb = K + (size_t)bh * LK_ * DK_;

#pragma unroll
    for (int i = 0; i < 8; i++) {
        int idx = tid + i * 256;
        int r = idx >> 4;
        int c4 = (idx & 15) << 2;
        float4 v = *(const float4*)&Qb[(size_t)(row0 + r) * 64 + c4];
        ushort4 h, l;
        split2(v.x, h.x, l.x); split2(v.y, h.y, l.y);
        split2(v.z, h.z, l.z); split2(v.w, h.w, l.w);
        *(ushort4*)&Qh[r * SC_STR + c4] = h;
        *(ushort4*)&Ql[r * SC_STR + c4] = l;
    }
#pragma unroll
    for (int i = 0; i < 16; i++) {
        int idx = tid + i * 256;
        int r = idx >> 4;
        int c4 = (idx & 15) << 2;
        float4 v = *(const float4*)&Kb[(size_t)(col0 + r) * 64 + c4];
        ushort4 h, l;
        split2(v.x, h.x, l.x); split2(v.y, h.y, l.y);
        split2(v.z, h.z, l.z); split2(v.w, h.w, l.w);
        *(ushort4*)&Kh[r * SC_STR + c4] = h;
        *(ushort4*)&Kl[r * SC_STR + c4] = l;
    }
    __syncthreads();

    const uint32_t qh_u = cvta_s(Qh), ql_u = cvta_s(Ql);
    const uint32_t kh_u = cvta_s(Kh), kl_u = cvta_s(Kl);
    const uint32_t aoff = ((wm * 32 + AROW(lane)) * SC_STR + ACOL(lane)) * 2;
    const uint32_t boff = ((wn * 64 + BROW(lane)) * SC_STR + BCOL(lane)) * 2;

    float* Sb = S + (size_t)bh * LQ_ * LK_;

    float rmA[2] = {-1e30f, -1e30f}, rsA[2] = {0.f, 0.f};
    float rmB[2] = {-1e30f, -1e30f}, rsB[2] = {0.f, 0.f};

#pragma unroll
    for (int ct = 0; ct < 2; ct++) {
        float acc[2][8][4];
#pragma unroll
        for (int i = 0; i < 2; i++)
#pragma unroll
            for (int j = 0; j < 8; j++)
#pragma unroll
                for (int t = 0; t < 4; t++) acc[i][j][t] = 0.f;

        const uint32_t ctoff = ct * (128 * SC_STR * 2);
#pragma unroll
        for (int ks = 0; ks < 4; ks++) {
            const uint32_t kb = ks * 32;
            uint32_t ah[2][4], al[2][4];
#pragma unroll
            for (int mi = 0; mi < 2; mi++) {
                ldsm_x4(ah[mi], qh_u + aoff + mi * (16 * SC_STR * 2) + kb);
                ldsm_x4(al[mi], ql_u + aoff + mi * (16 * SC_STR * 2) + kb);
            }
            uint32_t bhf[8][2], blf[8][2];
#pragma unroll
            for (int ni = 0; ni < 8; ni++) {
                ldsm_x2(bhf[ni], kh_u + ctoff + boff + ni * (8 * SC_STR * 2) + kb);
                ldsm_x2(blf[ni], kl_u + ctoff + boff + ni * (8 * SC_STR * 2) + kb);
            }
#pragma unroll
            for (int ni = 0; ni < 8; ni++)
#pragma unroll
                for (int mi = 0; mi < 2; mi++) {
                    mma16816(acc[mi][ni], ah[mi], bhf[ni]);
                    mma16816(acc[mi][ni], ah[mi], blf[ni]);
                    mma16816(acc[mi][ni], al[mi], bhf[ni]);
                }
        }

        // scale in place
#pragma unroll
        for (int i = 0; i < 2; i++)
#pragma unroll
            for (int j = 0; j < 8; j++)
#pragma unroll
                for (int t = 0; t < 4; t++) acc[i][j][t] *= 0.125f;

        // raw S store (shfl-widened float4)
#pragma unroll
        for (int mi = 0; mi < 2; mi++) {
#pragma unroll
            for (int ni = 0; ni < 8; ni++) {
                float c0 = acc[mi][ni][0], c1 = acc[mi][ni][1];
                float c2 = acc[mi][ni][2], c3 = acc[mi][ni][3];
                float p0 = __shfl_xor_sync(0xffffffffu, c0, 1);
                float p1 = __shfl_xor_sync(0xffffffffu, c1, 1);
                float p2 = __shfl_xor_sync(0xffffffffu, c2, 1);
                float p3 = __shfl_xor_sync(0xffffffffu, c3, 1);
                int row = row0 + wm * 32 + mi * 16 + gid;
                int colb = col0 + ct * 128 + wn * 64 + ni * 8 + (tig >> 1) * 4;
                if ((lane & 1) == 0) {
                    *(float4*)&Sb[(size_t)row * LK_ + colb] = make_float4(c0, c1, p0, p1);
                } else {
                    *(float4*)&Sb[(size_t)(row + 8) * LK_ + colb] = make_float4(p2, p3, c2, c3);
                }
            }
        }

        // per-row partial stats over this warp's 64 cols, merged across ct
#pragma unroll
        for (int mi = 0; mi < 2; mi++) {
            float mA = -1e30f, mB = -1e30f;
#pragma unroll
            for (int ni = 0; ni < 8; ni++) {
                mA = fmaxf(mA, fmaxf(acc[mi][ni][0], acc[mi][ni][1]));
                mB = fmaxf(mB, fmaxf(acc[mi][ni][2], acc[mi][ni][3]));
            }
            mA = fmaxf(mA, __shfl_xor_sync(0xffffffffu, mA, 1));
            mA = fmaxf(mA, __shfl_xor_sync(0xffffffffu, mA, 2));
            mB = fmaxf(mB, __shfl_xor_sync(0xffffffffu, mB, 1));
            mB = fmaxf(mB, __shfl_xor_sync(0xffffffffu, mB, 2));
            float sA = 0.f, sB = 0.f;
#pragma unroll
            for (int ni = 0; ni < 8; ni++) {
                sA += __expf(acc[mi][ni][0] - mA) + __expf(acc[mi][ni][1] - mA);
                sB += __expf(acc[mi][ni][2] - mB) + __expf(acc[mi][ni][3] - mB);
            }
            sA += __shfl_xor_sync(0xffffffffu, sA, 1);
            sA += __shfl_xor_sync(0xffffffffu, sA, 2);
            sB += __shfl_xor_sync(0xffffffffu, sB, 1);
            sB += __shfl_xor_sync(0xffffffffu, sB, 2);
            // merge running
            float nm = fmaxf(rmA[mi], mA);
            rsA[mi] = rsA[mi] * __expf(rmA[mi] - nm) + sA * __expf(mA - nm);
            rmA[mi] = nm;
            nm = fmaxf(rmB[mi], mB);
            rsB[mi] = rsB[mi] * __expf(rmB[mi] - nm) + sB * __expf(mB - nm);
            rmB[mi] = nm;
        }
    }

    if (tig == 0) {
#pragma unroll
        for (int mi = 0; mi < 2; mi++) {
            sst[wn][wm * 32 + mi * 16 + gid] = make_float2(rmA[mi], rsA[mi]);
            sst[wn][wm * 32 + mi * 16 + gid + 8] = make_float2(rmB[mi], rsB[mi]);
        }
    }
    __syncthreads();
    if (tid < 128) {
        float2 a = sst[0][tid], b = sst[1][tid];
        float M = fmaxf(a.x, b.x);
        float Ssum = a.y * __expf(a.x - M) + b.y * __expf(b.x - M);
        g_part[((size_t)(bh * 2048 + row0 + tid) << 3) + blockIdx.x] = make_float2(M, Ssum);
    }
}

// ============================================================================
// Stats reduce: 8 partials per row -> (max, 1/sum). Fixed order: deterministic.
// ============================================================================
__global__ void __launch_bounds__(256) stats_reduce()
{
    int row = blockIdx.x * 256 + threadIdx.x;
    const float2* p = &g_part[(size_t)row << 3];
    float M = -1e30f;
#pragma unroll
    for (int i = 0; i < 8; i++) M = fmaxf(M, p[i].x);
    float Ssum = 0.f;
#pragma unroll
    for (int i = 0; i < 8; i++) Ssum += p[i].y * __expf(p[i].x - M);
    g_ms[row] = make_float2(M, 1.0f / Ssum);
}

// ============================================================================
// Context (fused softmax): reads raw S, p = exp(s-m)*inv, writes attn in place,
// ctx = p @ V. 2 CTAs/SM, 2-deep LDG prefetch, chunked B-frags.
// ============================================================================
__global__ void __launch_bounds__(256, 2) ctx_tc(float* __restrict__ P,
                                                 const float* __restrict__ V)
{
    __shared__ unsigned short Ah[2][128][STRP], Al[2][128][STRP];
    __shared__ unsigned short Bh[2][64][STRP], Bl[2][64][STRP];
    __shared__ float2 ms[128];

    const int tid = threadIdx.x;
    const int wid = tid >> 5;
    const int lane = tid & 31;
    const int gid = lane >> 2;
    const int tig = lane & 3;
    const int bh = blockIdx.z;
    const int row0 = blockIdx.y * 128;
    float* Pb = P + (size_t)bh * LQ_ * LK_;
    const float* Vb = V + (size_t)bh * LK_ * DV_;

    if (tid < 128) ms[tid] = g_ms[bh * 2048 + row0 + tid];

    const uint32_t ah_u = cvta_s(Ah), al_u = cvta_s(Al);
    const uint32_t bh_u = cvta_s(Bh), bl_u = cvta_s(Bl);
    const uint32_t aoff = ((wid * 16 + AROW(lane)) * STRP + ACOL(lane)) * 2;
    const uint32_t boff = (BROW(lane) * STRP + BCOL(lane)) * 2;
    const uint32_t ABUF = 128 * STRP * 2;
    const uint32_t BBUF = 64 * STRP * 2;

    const int ar0 = tid >> 2;
    const int ac0 = (tid & 3) << 2;
    const int bn = tid & 63;
    const int bkg = (tid >> 6) << 2;

    __syncthreads();
    const float2 ms0 = ms[ar0];
    const float2 ms1 = ms[ar0 + 64];

    float acc[8][4];
#pragma unroll
    for (int j = 0; j < 8; j++)
#pragma unroll
        for (int t = 0; t < 4; t++) acc[j][t] = 0.f;

    const int NSTEP = LK_ / 16;  // 128

    // pending registers: vaP/vbP hold data for step s+1 (consumed at top of s)
    float4 vaP[2], vaN[2];
    float vbP[4], vbN[4];

    // prologue: step-0 data direct to smem buf0; prefetch step-1 into P regs
#pragma unroll
    for (int i = 0; i < 2; i++) {
        size_t off = (size_t)(row0 + ar0 + i * 64) * LK_ + ac0;
        float4 v = *(const float4*)&Pb[off];
        float2 mr = (i == 0) ? ms0 : ms1;
        v.x = __expf(v.x - mr.x) * mr.y;
        v.y = __expf(v.y - mr.x) * mr.y;
        v.z = __expf(v.z - mr.x) * mr.y;
        v.w = __expf(v.w - mr.x) * mr.y;
        *(float4*)&Pb[off] = v;
        ushort4 h, l;
        split2(v.x, h.x, l.x); split2(v.y, h.y, l.y);
        split2(v.z, h.z, l.z); split2(v.w, h.w, l.w);
        *(ushort4*)&Ah[0][ar0 + i * 64][ac0] = h;
        *(ushort4*)&Al[0][ar0 + i * 64][ac0] = l;
    }
    {
        float vb0[4];
#pragma unroll
        for (int j = 0; j < 4; j++) vb0[j] = Vb[(size_t)(bkg + j) * 64 + bn];
#pragma unroll
        for (int j = 0; j < 4; j++) split2(vb0[j], Bh[0][bn][bkg + j], Bl[0][bn][bkg + j]);
    }
#pragma unroll
    for (int i = 0; i < 2; i++)
        vaP[i] = *(const float4*)&Pb[(size_t)(row0 + ar0 + i * 64) * LK_ + 16 + ac0];
#pragma unroll
    for (int j = 0; j < 4; j++) vbP[j] = Vb[(size_t)(16 + bkg + j) * 64 + bn];
    __syncthreads();

    for (int s = 0; s < NSTEP; s++) {
        const int buf = s & 1;

        // consume pending (data for step s+1): exp, attn write, split -> buf^1
        if (s + 1 < NSTEP) {
            const int nb = buf ^ 1;
            const int k1 = (s + 1) * 16;
#pragma unroll
            for (int i = 0; i < 2; i++) {
                float4 v = vaP[i];
                float2 mr = (i == 0) ? ms0 : ms1;
                v.x = __expf(v.x - mr.x) * mr.y;
                v.y = __expf(v.y - mr.x) * mr.y;
                v.z = __expf(v.z - mr.x) * mr.y;
                v.w = __expf(v.w - mr.x) * mr.y;
                *(float4*)&Pb[(size_t)(row0 + ar0 + i * 64) * LK_ + k1 + ac0] = v;
                ushort4 h, l;
                split2(v.x, h.x, l.x); split2(v.y, h.y, l.y);
                split2(v.z, h.z, l.z); split2(v.w, h.w, l.w);
                *(ushort4*)&Ah[nb][ar0 + i * 64][ac0] = h;
                *(ushort4*)&Al[nb][ar0 + i * 64][ac0] = l;
            }
#pragma unroll
            for (int j = 0; j < 4; j++)
                split2(vbP[j], Bh[nb][bn][bkg + j], Bl[nb][bn][bkg + j]);
        }

        // issue LDG for step s+2
        if (s + 2 < NSTEP) {
            const int k2 = (s + 2) * 16;
#pragma unroll
            for (int i = 0; i < 2; i++)
                vaN[i] = *(const float4*)&Pb[(size_t)(row0 + ar0 + i * 64) * LK_ + k2 + ac0];
#pragma unroll
            for (int j = 0; j < 4; j++) vbN[j] = Vb[(size_t)(k2 + bkg + j) * 64 + bn];
        }

        // MMA on buf
        uint32_t ah[4], al[4];
        ldsm_x4(ah, ah_u + buf * ABUF + aoff);
        ldsm_x4(al, al_u + buf * ABUF + aoff);
#pragma unroll
        for (int ng = 0; ng < 2; ng++) {
            uint32_t bhf[4][2], blf[4][2];
#pragma unroll
            for (int j = 0; j < 4; j++) {
                ldsm_x2(bhf[j], bh_u + buf * BBUF + boff + (ng * 4 + j) * (8 * STRP * 2));
                ldsm_x2(blf[j], bl_u + buf * BBUF + boff + (ng * 4 + j) * (8 * STRP * 2));
            }
#pragma unroll
            for (int j = 0; j < 4; j++) {
                mma16816(acc[ng * 4 + j], ah, bhf[j]);
                mma16816(acc[ng * 4 + j], ah, blf[j]);
                mma16816(acc[ng * 4 + j], al, bhf[j]);
            }
        }

        // rotate pending regs
#pragma unroll
        for (int i = 0; i < 2; i++) vaP[i] = vaN[i];
#pragma unroll
        for (int j = 0; j < 4; j++) vbP[j] = vbN[j];
        __syncthreads();
    }

    const int b = bh >> 4, hh = bh & 15;
#pragma unroll
    for (int ni = 0; ni < 8; ni++) {
        int row = row0 + wid * 16 + gid;
        int col = hh * 64 + ni * 8 + 2 * tig;
        *(float2*)&g_ctx[(size_t)(b * 2048 + row) * 1024 + col] =
            make_float2(acc[ni][0], acc[ni][1]);
        *(float2*)&g_ctx[(size_t)(b * 2048 + row + 8) * 1024 + col] =
            make_float2(acc[ni][2], acc[ni][3]);
    }
}

// ============================================================================
// Output projection: out = ctx @ wo; M=8192, N=K=1024. 2 CTAs/SM, chunked B.
// ============================================================================
__global__ void __launch_bounds__(256, 2) outproj_tc(const float* __restrict__ W,
                                                     float* __restrict__ C)
{
    __shared__ unsigned short Ah[2][128][STRP], Al[2][128][STRP];
    __shared__ unsigned short Bh[2][128][STRP], Bl[2][128][STRP];

    const int tid = threadIdx.x;
    const int wid = tid >> 5;
    const int lane = tid & 31;
    const int gid = lane >> 2;
    const int tig = lane & 3;
    const int wm = wid & 3;
    const int wn = wid >> 2;
    const int row0 = blockIdx.y * 128;
    const int col0 = blockIdx.x * 128;

    const uint32_t ah_u = cvta_s(Ah), al_u = cvta_s(Al);
    const uint32_t bh_u = cvta_s(Bh), bl_u = cvta_s(Bl);
    const uint32_t aoff = ((wm * 32 + AROW(lane)) * STRP + ACOL(lane)) * 2;
    const uint32_t boff = ((wn * 64 + BROW(lane)) * STRP + BCOL(lane)) * 2;
    const uint32_t BUFB = 128 * STRP * 2;

    const int ar0 = tid >> 2;
    const int ac0 = (tid & 3) << 2;
    const int bn = tid & 127;
    const int bkg = (tid >> 7) << 3;

    float acc[2][8][4];
#pragma unroll
    for (int i = 0; i < 2; i++)
#pragma unroll
        for (int j = 0; j < 8; j++)
#pragma unroll
            for (int t = 0; t < 4; t++) acc[i][j][t] = 0.f;

    float4 va[2];
    float vb[8];

#pragma unroll
    for (int i = 0; i < 2; i++)
        va[i] = *(const float4*)&g_ctx[(size_t)(row0 + ar0 + i * 64) * DM_ + ac0];
#pragma unroll
    for (int j = 0; j < 8; j++) vb[j] = W[(size_t)(bkg + j) * DM_ + col0 + bn];
#pragma unroll
    for (int i = 0; i < 2; i++) {
        ushort4 h, l;
        split2(va[i].x, h.x, l.x); split2(va[i].y, h.y, l.y);
        split2(va[i].z, h.z, l.z); split2(va[i].w, h.w, l.w);
        *(ushort4*)&Ah[0][ar0 + i * 64][ac0] = h;
        *(ushort4*)&Al[0][ar0 + i * 64][ac0] = l;
    }
#pragma unroll
    for (int j = 0; j < 8; j++) split2(vb[j], Bh[0][bn][bkg + j], Bl[0][bn][bkg + j]);
    __syncthreads();

    const int NSTEP = DM_ / 16;
    for (int s = 0; s < NSTEP; s++) {
        const int buf = s & 1;
        const int k1 = (s + 1) * 16;
        if (s + 1 < NSTEP) {
#pragma unroll
            for (int i = 0; i < 2; i++)
                va[i] = *(const float4*)&g_ctx[(size_t)(row0 + ar0 + i * 64) * DM_ + k1 + ac0];
#pragma unroll
            for (int j = 0; j < 8; j++) vb[j] = W[(size_t)(k1 + bkg + j) * DM_ + col0 + bn];
        }

        const uint32_t ab = buf * BUFB;
        uint32_t ah[2][4], al[2][4];
#pragma unroll
        for (int mi = 0; mi < 2; mi++) {
            ldsm_x4(ah[mi], ah_u + ab + aoff + mi * (16 * STRP * 2));
            ldsm_x4(al[mi], al_u + ab + aoff + mi * (16 * STRP * 2));
        }
#pragma unroll
        for (int ng = 0; ng < 2; ng++) {
            uint32_t bhf[4][2], blf[4][2];
#pragma unroll
            for (int j = 0; j < 4; j++) {
                ldsm_x2(bhf[j], bh_u + ab + boff + (ng * 4 + j) * (8 * STRP * 2));
                ldsm_x2(blf[j], bl_u + ab + boff + (ng * 4 + j) * (8 * STRP * 2));
            }
#pragma unroll
            for (int j = 0; j < 4; j++)
#pragma unroll
                for (int mi = 0; mi < 2; mi++) {
                    mma16816(acc[mi][ng * 4 + j], ah[mi], bhf[j]);
                    mma16816(acc[mi][ng * 4 + j], ah[mi], blf[j]);
                    mma16816(acc[mi][ng * 4 + j], al[mi], bhf[j]);
                }
        }

        if (s + 1 < NSTEP) {
            const int nb = buf ^ 1;
#pragma unroll
            for (int i = 0; i < 2; i++) {
                ushort4 h, l;
                split2(va[i].x, h.x, l.x); split2(va[i].y, h.y, l.y);
                split2(va[i].z, h.z, l.z); split2(va[i].w, h.w, l.w);
                *(ushort4*)&Ah[nb][ar0 + i * 64][ac0] = h;
                *(ushort4*)&Al[nb][ar0 + i * 64][ac0] = l;
            }
#pragma unroll
            for (int j = 0; j < 8; j++)
                split2(vb[j], Bh[nb][bn][bkg + j], Bl[nb][bn][bkg + j]);
        }
        __syncthreads();
    }

#pragma unroll
    for (int mi = 0; mi < 2; mi++) {
#pragma unroll
        for (int ni = 0; ni < 8; ni++) {
            int row = row0 + wm * 32 + mi * 16 + gid;
            int col = col0 + wn * 64 + ni * 8 + 2 * tig;
            *(float2*)&C[(size_t)row * DM_ + col] =
                make_float2(acc[mi][ni][0], acc[mi][ni][1]);
            *(float2*)&C[(size_t)(row + 8) * DM_ + col] =
                make_float2(acc[mi][ni][2], acc[mi][ni][3]);
        }
    }
}

// ============================================================================
// Launch
// ============================================================================
extern "C" void kernel_launch(void* const* d_in, const int* in_sizes, int n_in,
                              void* d_out, int out_size)
{
    const float* q  = (const float*)d_in[0];
    const float* k  = (const float*)d_in[1];
    const float* v  = (const float*)d_in[2];
    const float* wq = (const float*)d_in[3];
    const float* wk = (const float*)d_in[4];
    const float* wv = (const float*)d_in[5];
    const float* wo = (const float*)d_in[6];
    float* out = (float*)d_out;

    const long long OUT_E = (long long)B_ * LQ_ * DM_;        // 8,388,608
    const long long ATT_E = (long long)B_ * H_ * LQ_ * LK_;   // 268,435,456

    float* attn;
    if ((long long)out_size >= OUT_E + ATT_E) {
        attn = out + OUT_E;                 // tuple output: [out, attn]
    } else {
        void* p = nullptr;
        cudaGetSymbolAddress(&p, g_attn_fb);
        attn = (float*)p;
    }

    float *gq, *gk, *gv;
    cudaGetSymbolAddress((void**)&gq, g_Q);
    cudaGetSymbolAddress((void**)&gk, g_K);
    cudaGetSymbolAddress((void**)&gv, g_V);

    cudaFuncSetAttribute(scores_tc,
                         cudaFuncAttributeMaxDynamicSharedMemorySize, SC_SMEM_BYTES);

    dim3 t(256);
    proj_tc<<<dim3(8, 64), t>>>(q, wq, gq);
    proj_tc<<<dim3(8, 64), t>>>(k, wk, gk);
    proj_tc<<<dim3(8, 64), t>>>(v, wv, gv);
    scores_tc<<<dim3(8, 16, 64), t, SC_SMEM_BYTES>>>(gq, gk, attn);
    stats_reduce<<<dim3(NROWS / 256), t>>>();
    ctx_tc<<<dim3(1, 16, 64), t>>>(attn, gv);
    outproj_tc<<<dim3(8, 64), t>>>(wo, out);
}